// round 14
// baseline (speedup 1.0000x reference)
#include <cuda_runtime.h>
#include <cuda_bf16.h>
#include <cstdint>
#include <math.h>

#define TSTEPS 2048
#define NNODE  100
#define FIN    128
#define HID    512
#define NCTAN  64
#define NCTA   128
#define NTH    128              // 4 warps
#define CHUNKB 17408            // 64 rows x 272 bytes, contiguous

// SMEM layout
#define HS_OFF   0
#define HS_BYTES (4*CHUNKB)                 // 69632
#define XS_OFF   HS_BYTES                   // 69632
#define XS_BYTES CHUNKB                     // 17408
#define BF_OFF   (XS_OFF+XS_BYTES)          // 87040
#define BF_BYTES (3*40*32*8)                // 30720
#define BIAS_OFF (BF_OFF+BF_BYTES)          // 117760
#define MBAR_OFF (BIAS_OFF+128)             // 117888, 5 mbarriers
#define SMEM_TOTAL (MBAR_OFF+64)            // 117952

// ---------------- persistent device scratch ----------------
__device__ __align__(1024) __nv_bfloat16 g_xb2[TSTEPS][2][64][136];
__device__ __align__(1024) __nv_bfloat16 g_hb2[2][2][4][64][136];
__device__ uint2 g_bpack[NCTAN][3*40*32];
__device__ unsigned long long g_prodf[TSTEPS + 1][2];  // packed 4x16-bit producer counts
__device__ unsigned long long g_ackf[TSTEPS][2];       // consumer completion counts
__device__ float g_gnn[NNODE][704];
__device__ int   g_tgt[NNODE*8];
__device__ int   g_srcl[NNODE][NNODE];
__device__ int   g_cnt[NNODE];
__device__ float g_h1[NNODE][256];
__device__ float g_g2[NNODE][128];

// ---------------- helpers ----------------
__device__ __forceinline__ uint32_t s2u(const void* p) {
    return (uint32_t)__cvta_generic_to_shared(p);
}
__device__ __forceinline__ uint32_t pk2(float lo, float hi) {
    uint32_t l = (uint32_t)__bfloat16_as_ushort(__float2bfloat16_rn(lo));
    uint32_t h = (uint32_t)__bfloat16_as_ushort(__float2bfloat16_rn(hi));
    return l | (h << 16);
}
__device__ __forceinline__ void ldsmx4(uint32_t s, uint32_t& a0, uint32_t& a1,
                                       uint32_t& a2, uint32_t& a3) {
    asm volatile("ldmatrix.sync.aligned.m8n8.x4.shared.b16 {%0,%1,%2,%3}, [%4];\n"
                 : "=r"(a0), "=r"(a1), "=r"(a2), "=r"(a3) : "r"(s));
}
__device__ __forceinline__ void mma16816(float* c, uint32_t a0, uint32_t a1,
                                         uint32_t a2, uint32_t a3,
                                         uint32_t b0, uint32_t b1) {
    asm volatile("mma.sync.aligned.m16n8k16.row.col.f32.bf16.bf16.f32 "
                 "{%0,%1,%2,%3},{%4,%5,%6,%7},{%8,%9},{%0,%1,%2,%3};\n"
                 : "+f"(c[0]), "+f"(c[1]), "+f"(c[2]), "+f"(c[3])
                 : "r"(a0), "r"(a1), "r"(a2), "r"(a3), "r"(b0), "r"(b1));
}
__device__ __forceinline__ float fsig(float x) {
    float e;
    asm("ex2.approx.f32 %0, %1;" : "=f"(e) : "f"(-1.4426950408889634f * x));
    float r;
    asm("rcp.approx.f32 %0, %1;" : "=f"(r) : "f"(1.0f + e));
    return r;
}
__device__ __forceinline__ float ftanh(float x) {
    float e;
    asm("ex2.approx.f32 %0, %1;" : "=f"(e) : "f"(2.8853900817779268f * x));
    float r;
    asm("rcp.approx.f32 %0, %1;" : "=f"(r) : "f"(1.0f + e));
    return 1.0f - 2.0f * r;
}
// mbarrier ops (CTA-local; no clusters)
__device__ __forceinline__ void minit(uint32_t mbar, uint32_t cnt) {
    asm volatile("mbarrier.init.shared::cta.b64 [%0], %1;" :: "r"(mbar), "r"(cnt) : "memory");
}
__device__ __forceinline__ void mexpect(uint32_t mbar, uint32_t bytes) {
    asm volatile("mbarrier.arrive.expect_tx.shared::cta.b64 _, [%0], %1;"
                 :: "r"(mbar), "r"(bytes) : "memory");
}
__device__ __forceinline__ void mwait(uint32_t mbar, uint32_t ph) {
    asm volatile("{\n\t.reg .pred P;\n"
        "W%=:\n\tmbarrier.try_wait.parity.acquire.cta.shared::cta.b64 P, [%0], %1, 0x989680;\n"
        "\t@P bra D%=;\n\tbra W%=;\nD%=:\n\t}"
        :: "r"(mbar), "r"(ph) : "memory");
}
__device__ __forceinline__ void bulk1d(uint32_t dst, const void* src, uint32_t bytes,
                                       uint32_t mbar) {
    asm volatile("cp.async.bulk.shared::cta.global.mbarrier::complete_tx::bytes "
                 "[%0], [%1], %2, [%3];"
                 :: "r"(dst), "l"(src), "r"(bytes), "r"(mbar) : "memory");
}
__device__ __forceinline__ void fence_async() {
    asm volatile("fence.proxy.async.shared::cta;" ::: "memory");
}
__device__ __forceinline__ unsigned long long ldacq(const unsigned long long* p) {
    unsigned long long v;
    asm volatile("ld.acquire.gpu.u64 %0, [%1];" : "=l"(v) : "l"(p) : "memory");
    return v;
}
__device__ __forceinline__ void addrel(unsigned long long* p, unsigned long long v) {
    unsigned long long old;
    asm volatile("atom.add.release.gpu.u64 %0, [%1], %2;"
                 : "=l"(old) : "l"(p), "l"(v) : "memory");
}

// ---------------- phase 0 ----------------
__global__ void prep_x(const float* __restrict__ x) {
    int t = blockIdx.x;
    for (int i = threadIdx.x; i < 2 * 64 * 136; i += blockDim.x) {
        int mh  = i / (64 * 136);
        int rem = i % (64 * 136);
        int r = rem / 136, f = rem % 136;
        int row = mh * 64 + r;
        float v = (row < NNODE && f < FIN) ? x[(t * NNODE + row) * FIN + f] : 0.0f;
        g_xb2[t][mh][r][f] = __float2bfloat16_rn(v);
    }
    // zero/seed dataflow flags every launch (stream-ordered before gru)
    if (threadIdx.x == 0) {
        g_prodf[t + 1][0] = 0ULL; g_prodf[t + 1][1] = 0ULL;
        g_ackf[t][0] = 0ULL;      g_ackf[t][1] = 0ULL;
        if (t == 0) {
            g_prodf[0][0] = 0x0010001000100010ULL;   // h0 (zeros) "already produced"
            g_prodf[0][1] = 0x0010001000100010ULL;
        }
    }
}

__global__ void prep_w(const float* __restrict__ Wih, const float* __restrict__ Whh) {
    int c = blockIdx.x;   // 64 column groups
    for (int e = threadIdx.x; e < 3840; e += blockDim.x) {
        int tau = e / 1280;
        int rem = e % 1280;
        int s = rem / 32;
        int l = rem % 32;
        int t = l & 3, g = l >> 2;
        int col = tau * HID + c * 8 + g;
        uint32_t b0, b1;
        if (s < 32) {
            const float* wr = Whh + (size_t)col * HID + s * 16 + t * 2;
            b0 = pk2(wr[0], wr[1]);
            b1 = pk2(wr[8], wr[9]);
        } else {
            const float* wr = Wih + (size_t)col * FIN + (s - 32) * 16 + t * 2;
            b0 = pk2(wr[0], wr[1]);
            b1 = pk2(wr[8], wr[9]);
        }
        g_bpack[c][e] = make_uint2(b0, b1);
    }
    // zero BOTH h buffers exactly (69632 u32 total / 64 blocks = 1088 each)
    uint32_t* hb = (uint32_t*)&g_hb2[0][0][0][0][0];
    for (int i = threadIdx.x; i < 1088; i += blockDim.x)
        hb[c * 1088 + i] = 0u;
}

// ---------------- persistent GRU (dataflow-synced, bulk-async broadcast) ----------------
__global__ void __launch_bounds__(NTH, 1) gru_persistent(
    const float* __restrict__ bih, const float* __restrict__ bhh)
{
    extern __shared__ char sm[];
    char* hS     = sm + HS_OFF;
    char* xS     = sm + XS_OFF;
    uint2* bfS   = (uint2*)(sm + BF_OFF);
    float* biasS = (float*)(sm + BIAS_OFF);
    const uint32_t mb = s2u(sm + MBAR_OFF);   // h: mb+0..24, x: mb+32

    const int tid = threadIdx.x;
    const int w   = tid >> 5;
    const int l   = tid & 31;
    const int m   = (int)(blockIdx.x >> 6);   // row half
    const int gG  = (int)(blockIdx.x & 63);   // column group
    const unsigned long long mytok = 1ULL << (16 * (gG >> 4));

    // ---- one-time init ----
    {
        const uint32_t* src = (const uint32_t*)&g_bpack[gG][0];
        uint32_t* dst = (uint32_t*)bfS;
        for (int i = tid; i < BF_BYTES / 4; i += NTH) dst[i] = src[i];
        if (tid < 32) {
            int hu = gG * 8 + (tid & 7);
            int sec = tid >> 3;
            float v;
            if (sec == 0)      v = bih[hu] + bhh[hu];
            else if (sec == 1) v = bih[HID + hu] + bhh[HID + hu];
            else if (sec == 2) v = bhh[2 * HID + hu];
            else               v = bih[2 * HID + hu];
            biasS[tid] = v;
        }
        if (tid == 0) {
            #pragma unroll
            for (int k = 0; k < 5; k++) minit(mb + 8 * k, 1);
        }
    }
    fence_async();
    __syncthreads();
    // prefetch x for step 0
    if (tid == 0) {
        mexpect(mb + 32, CHUNKB);
        bulk1d(s2u(xS), &g_xb2[0][m][0][0], CHUNKB, mb + 32);
    }

    const int rb = w * 16;
    const int gl = l >> 2;
    const int t  = l & 3;
    const int r0g = m * 64 + rb + gl;
    const int r1g = r0g + 8;
    const int colg = gG * 8 + t * 2;
    const int ri0 = r0g & 63, ri1 = r1g & 63;
    const int hcw = colg >> 7, hcc = colg & 127;

    const int arow = rb + (l & 15);
    const uint32_t aBase = (uint32_t)(arow * 272 + ((l >> 4) & 1) * 16);
    const uint32_t aH = s2u(hS) + aBase;
    const uint32_t aX = s2u(xS) + aBase;

    const float brA = biasS[t * 2],      brB = biasS[t * 2 + 1];
    const float bzA = biasS[8 + t * 2],  bzB = biasS[8 + t * 2 + 1];
    const float bhA = biasS[16 + t * 2], bhB = biasS[16 + t * 2 + 1];
    const float bxA = biasS[24 + t * 2], bxB = biasS[24 + t * 2 + 1];

    float hm0 = 0.f, hm1 = 0.f, hm2 = 0.f, hm3 = 0.f;
    const uint32_t hS_s = s2u(hS);

    for (int step = 0; step < TSTEPS; step++) {
        const int cur = step & 1, nxt = cur ^ 1;
        const uint32_t ph = (uint32_t)(step & 1);

        float accR[4]  = {0.f, 0.f, 0.f, 0.f};
        float accZ[4]  = {0.f, 0.f, 0.f, 0.f};
        float accHN[4] = {0.f, 0.f, 0.f, 0.f};
        float accXN[4] = {0.f, 0.f, 0.f, 0.f};
        uint32_t a0, a1, a2, a3;

        // ---- tid0: issue h chunk bulks as their 16 producers finish ----
        if (tid == 0) {
            unsigned long long v = 0;
            #pragma unroll
            for (int c = 0; c < 4; c++) {
                while (((v >> (16 * c)) & 0xFFFFULL) < 16ULL)
                    v = ldacq(&g_prodf[step][m]);
                mexpect(mb + 8 * c, CHUNKB);
                bulk1d(hS_s + c * CHUNKB, &g_hb2[cur][m][c][0][0], CHUNKB, mb + 8 * c);
            }
        }

        // ---- x part (prefetched previous step) ----
        mwait(mb + 32, ph);
        #pragma unroll
        for (int j = 0; j < 8; j++) {
            int s = 32 + j;
            ldsmx4(aX + (uint32_t)(j * 32), a0, a1, a2, a3);
            uint2 br = bfS[(0 * 40 + s) * 32 + l];
            uint2 bz = bfS[(1 * 40 + s) * 32 + l];
            uint2 bn = bfS[(2 * 40 + s) * 32 + l];
            mma16816(accR,  a0, a1, a2, a3, br.x, br.y);
            mma16816(accZ,  a0, a1, a2, a3, bz.x, bz.y);
            mma16816(accXN, a0, a1, a2, a3, bn.x, bn.y);
        }

        // ---- h chunks, pipelined ----
        #pragma unroll
        for (int c = 0; c < 4; c++) {
            mwait(mb + 8 * c, ph);
            if (c == 3 && tid == 0)            // all 4 bulks complete -> global buf free
                addrel(&g_ackf[step][m], 1ULL);
            #pragma unroll
            for (int j = 0; j < 8; j++) {
                int s = c * 8 + j;
                ldsmx4(aH + (uint32_t)(c * CHUNKB + j * 32), a0, a1, a2, a3);
                uint2 br = bfS[(0 * 40 + s) * 32 + l];
                uint2 bz = bfS[(1 * 40 + s) * 32 + l];
                uint2 bn = bfS[(2 * 40 + s) * 32 + l];
                mma16816(accR,  a0, a1, a2, a3, br.x, br.y);
                mma16816(accZ,  a0, a1, a2, a3, bz.x, bz.y);
                mma16816(accHN, a0, a1, a2, a3, bn.x, bn.y);
            }
        }

        // ---- gates (fp32 master h, MUFU approx) ----
        {
            float r = fsig(accR[0] + brA), z = fsig(accZ[0] + bzA);
            float n = ftanh(accXN[0] + bxA + r * (accHN[0] + bhA));
            hm0 = (1.f - z) * n + z * hm0;
        }
        {
            float r = fsig(accR[1] + brB), z = fsig(accZ[1] + bzB);
            float n = ftanh(accXN[1] + bxB + r * (accHN[1] + bhB));
            hm1 = (1.f - z) * n + z * hm1;
        }
        {
            float r = fsig(accR[2] + brA), z = fsig(accZ[2] + bzA);
            float n = ftanh(accXN[2] + bxA + r * (accHN[2] + bhA));
            hm2 = (1.f - z) * n + z * hm2;
        }
        {
            float r = fsig(accR[3] + brB), z = fsig(accZ[3] + bzB);
            float n = ftanh(accXN[3] + bxB + r * (accHN[3] + bhB));
            hm3 = (1.f - z) * n + z * hm3;
        }

        // ---- anti-dependence: target buffer was read at step-1; wait those reads done
        if (tid == 0 && step >= 1) {
            while (ldacq(&g_ackf[step - 1][m]) < 64ULL) { }
        }
        __syncthreads();

        // ---- publish next h (real rows only; chunked padded layout) ----
        if (r0g < NNODE) *(uint32_t*)&g_hb2[nxt][m][hcw][ri0][hcc] = pk2(hm0, hm1);
        if (r1g < NNODE) *(uint32_t*)&g_hb2[nxt][m][hcw][ri1][hcc] = pk2(hm2, hm3);

        if (step == TSTEPS - 1) {
            if (r0g < NNODE) { g_gnn[r0g][colg] = hm0; g_gnn[r0g][colg + 1] = hm1; }
            if (r1g < NNODE) { g_gnn[r1g][colg] = hm2; g_gnn[r1g][colg + 1] = hm3; }
        }

        __syncthreads();
        if (tid == 0) {
            if (step + 1 < TSTEPS) {
                // prefetch next x (all x MMAs of this step finished at the sync above)
                mexpect(mb + 32, CHUNKB);
                bulk1d(s2u(xS), &g_xb2[step + 1][m][0][0], CHUNKB, mb + 32);
                // signal: this CTA's slice of h(step+1) is published
                addrel(&g_prodf[step + 1][m], mytok);
            }
        }
    }
}

// ---------------- GNN tail ----------------
__global__ void flat_emb_k(const float* __restrict__ flat, const float* __restrict__ fW,
                           const float* __restrict__ fb, const float* __restrict__ emb) {
    int n = blockIdx.x;
    int o = threadIdx.x;
    float s = fb[o];
    #pragma unroll
    for (int j = 0; j < 32; j++) s += flat[n * 32 + j] * fW[o * 32 + j];
    g_gnn[n][512 + o] = s;
    for (int j = o; j < 128; j += 64) g_gnn[n][576 + j] = emb[n * 128 + j];
}

__global__ void knn_k(const float* __restrict__ emb) {
    __shared__ float eu[128];
    __shared__ float sim[NNODE];
    int u = blockIdx.x;
    eu[threadIdx.x] = emb[u * 128 + threadIdx.x];
    __syncthreads();
    if (threadIdx.x < NNODE) {
        int v = threadIdx.x;
        float d = 0.f, nu = 0.f, nv = 0.f;
        for (int f = 0; f < 128; f++) {
            float a = eu[f], b = emb[v * 128 + f];
            d += a * b; nu += a * a; nv += b * b;
        }
        float s = d / (fmaxf(sqrtf(nu), 1e-8f) * fmaxf(sqrtf(nv), 1e-8f));
        sim[v] = (v == u) ? 0.0f : s;
    }
    __syncthreads();
    if (threadIdx.x == 0) {
        for (int i = 0; i < 8; i++) {
            float best = -1e30f; int bi = 0;
            for (int v = 0; v < NNODE; v++)
                if (sim[v] > best) { best = sim[v]; bi = v; }
            g_tgt[u * 8 + i] = bi;
            sim[bi] = -2e30f;
        }
    }
}

__global__ void build_adj_k() {
    int v = threadIdx.x;
    if (v < NNODE) {
        int c = 0;
        for (int e = 0; e < NNODE * 8; e++)
            if (g_tgt[e] == v) g_srcl[v][c++] = e >> 3;
        g_cnt[v] = c;
    }
}

__global__ void sage1_k(const float* __restrict__ Wl, const float* __restrict__ Wr,
                        const float* __restrict__ b) {
    __shared__ float agg[704];
    __shared__ float xv[704];
    __shared__ int srcl[NNODE];
    __shared__ int scnt;
    int v = blockIdx.x;
    if (threadIdx.x == 0) scnt = g_cnt[v];
    if (threadIdx.x < NNODE) srcl[threadIdx.x] = g_srcl[v][threadIdx.x];
    __syncthreads();
    int cnt = scnt;
    float inv = 1.0f / fmaxf((float)cnt, 1.0f);
    for (int d = threadIdx.x; d < 704; d += blockDim.x) {
        float a = 0.f;
        for (int i = 0; i < cnt; i++) a += g_gnn[srcl[i]][d];
        agg[d] = a * inv;
        xv[d] = g_gnn[v][d];
    }
    __syncthreads();
    int o = threadIdx.x;
    float s = b[o];
    for (int d = 0; d < 704; d++)
        s += Wl[o * 704 + d] * agg[d] + Wr[o * 704 + d] * xv[d];
    g_h1[v][o] = fmaxf(s, 0.0f);
}

__global__ void sage2_k(const float* __restrict__ Wl, const float* __restrict__ Wr,
                        const float* __restrict__ b) {
    __shared__ float agg[256];
    __shared__ float xv[256];
    __shared__ int srcl[NNODE];
    __shared__ int scnt;
    int v = blockIdx.x;
    if (threadIdx.x == 0) scnt = g_cnt[v];
    if (threadIdx.x < NNODE) srcl[threadIdx.x] = g_srcl[v][threadIdx.x];
    __syncthreads();
    int cnt = scnt;
    float inv = 1.0f / fmaxf((float)cnt, 1.0f);
    {
        int d = threadIdx.x;
        float a = 0.f;
        for (int i = 0; i < cnt; i++) a += g_h1[srcl[i]][d];
        agg[d] = a * inv;
        xv[d] = g_h1[v][d];
    }
    __syncthreads();
    if (threadIdx.x < 128) {
        int o = threadIdx.x;
        float s = b[o];
        for (int d = 0; d < 256; d++)
            s += Wl[o * 256 + d] * agg[d] + Wr[o * 256 + d] * xv[d];
        g_g2[v][o] = s;
    }
}

__global__ void out_k(const float* __restrict__ oW, const float* __restrict__ ob,
                      float* __restrict__ out) {
    __shared__ float red[4];
    int v = blockIdx.x;
    float s = 0.f;
    for (int i = threadIdx.x; i < 640; i += 128) {
        float f = (i < 128) ? g_g2[v][i] : g_gnn[v][i - 128];
        s += oW[i] * f;
    }
    for (int off = 16; off > 0; off >>= 1) s += __shfl_down_sync(0xffffffffu, s, off);
    if ((threadIdx.x & 31) == 0) red[threadIdx.x >> 5] = s;
    __syncthreads();
    if (threadIdx.x == 0) {
        float tot = red[0] + red[1] + red[2] + red[3] + ob[0];
        out[v] = 1.0f / (1.0f + expf(-tot));
    }
}

// ---------------- launch ----------------
extern "C" void kernel_launch(void* const* d_in, const int* in_sizes, int n_in,
                              void* d_out, int out_size) {
    const float* node_feat = (const float*)d_in[0];
    const float* flat      = (const float*)d_in[1];
    const float* emb       = (const float*)d_in[2];
    const float* gru_Wih   = (const float*)d_in[3];
    const float* gru_Whh   = (const float*)d_in[4];
    const float* gru_bih   = (const float*)d_in[5];
    const float* gru_bhh   = (const float*)d_in[6];
    const float* flat_W    = (const float*)d_in[7];
    const float* flat_b    = (const float*)d_in[8];
    const float* sage1_Wl  = (const float*)d_in[9];
    const float* sage1_Wr  = (const float*)d_in[10];
    const float* sage1_b   = (const float*)d_in[11];
    const float* sage2_Wl  = (const float*)d_in[12];
    const float* sage2_Wr  = (const float*)d_in[13];
    const float* sage2_b   = (const float*)d_in[14];
    const float* out_W     = (const float*)d_in[15];
    const float* out_b     = (const float*)d_in[16];
    float* out = (float*)d_out;

    static bool attr_set = false;
    if (!attr_set) {
        cudaFuncSetAttribute(gru_persistent,
                             cudaFuncAttributeMaxDynamicSharedMemorySize, SMEM_TOTAL);
        attr_set = true;
    }

    prep_x<<<TSTEPS, 256>>>(node_feat);
    prep_w<<<NCTAN, 256>>>(gru_Wih, gru_Whh);
    flat_emb_k<<<NNODE, 64>>>(flat, flat_W, flat_b, emb);
    knn_k<<<NNODE, 128>>>(emb);
    build_adj_k<<<1, 128>>>();
    gru_persistent<<<NCTA, NTH, SMEM_TOTAL>>>(gru_bih, gru_bhh);
    sage1_k<<<NNODE, 256>>>(sage1_Wl, sage1_Wr, sage1_b);
    sage2_k<<<NNODE, 256>>>(sage2_Wl, sage2_Wr, sage2_b);
    out_k<<<NNODE, 128>>>(out_W, out_b, out);
}

// round 16
// speedup vs baseline: 1.7200x; 1.7200x over previous
#include <cuda_runtime.h>
#include <cuda_bf16.h>
#include <cstdint>
#include <math.h>

#define TSTEPS 2048
#define NNODE  100
#define FIN    128
#define HID    512
#define NCTAN  64
#define NCTA   128
#define NTH    128              // 4 warps
#define CHUNKB 17408            // 64 rows x 272 bytes, contiguous

// SMEM layout
#define HS_OFF   0
#define HS_BYTES (4*CHUNKB)                 // 69632
#define XS_OFF   HS_BYTES                   // 69632
#define XS_BYTES CHUNKB                     // 17408
#define BF_OFF   (XS_OFF+XS_BYTES)          // 87040
#define BF_BYTES (3*40*32*8)                // 30720
#define BIAS_OFF (BF_OFF+BF_BYTES)          // 117760
#define MBAR_OFF (BIAS_OFF+128)             // 117888, 5 mbarriers
#define SMEM_TOTAL (MBAR_OFF+64)            // 117952

// ---------------- persistent device scratch ----------------
__device__ __align__(1024) __nv_bfloat16 g_xb2[TSTEPS][2][64][136];
__device__ __align__(1024) __nv_bfloat16 g_hb2[2][2][4][64][136];
__device__ uint2 g_bpack[NCTAN][3*40*32];
__device__ unsigned long long g_bar[TSTEPS + 2];      // monotonic barrier counters
__device__ float g_gnn[NNODE][704];
__device__ int   g_tgt[NNODE*8];
__device__ int   g_srcl[NNODE][NNODE];
__device__ int   g_cnt[NNODE];
__device__ float g_h1[NNODE][256];
__device__ float g_g2[NNODE][128];

// ---------------- helpers ----------------
__device__ __forceinline__ uint32_t s2u(const void* p) {
    return (uint32_t)__cvta_generic_to_shared(p);
}
__device__ __forceinline__ uint32_t pk2(float lo, float hi) {
    uint32_t l = (uint32_t)__bfloat16_as_ushort(__float2bfloat16_rn(lo));
    uint32_t h = (uint32_t)__bfloat16_as_ushort(__float2bfloat16_rn(hi));
    return l | (h << 16);
}
__device__ __forceinline__ void ldsmx4(uint32_t s, uint32_t& a0, uint32_t& a1,
                                       uint32_t& a2, uint32_t& a3) {
    asm volatile("ldmatrix.sync.aligned.m8n8.x4.shared.b16 {%0,%1,%2,%3}, [%4];\n"
                 : "=r"(a0), "=r"(a1), "=r"(a2), "=r"(a3) : "r"(s));
}
__device__ __forceinline__ void mma16816(float* c, uint32_t a0, uint32_t a1,
                                         uint32_t a2, uint32_t a3,
                                         uint32_t b0, uint32_t b1) {
    asm volatile("mma.sync.aligned.m16n8k16.row.col.f32.bf16.bf16.f32 "
                 "{%0,%1,%2,%3},{%4,%5,%6,%7},{%8,%9},{%0,%1,%2,%3};\n"
                 : "+f"(c[0]), "+f"(c[1]), "+f"(c[2]), "+f"(c[3])
                 : "r"(a0), "r"(a1), "r"(a2), "r"(a3), "r"(b0), "r"(b1));
}
__device__ __forceinline__ float fsig(float x) {
    float e;
    asm("ex2.approx.f32 %0, %1;" : "=f"(e) : "f"(-1.4426950408889634f * x));
    float r;
    asm("rcp.approx.f32 %0, %1;" : "=f"(r) : "f"(1.0f + e));
    return r;
}
__device__ __forceinline__ float ftanh(float x) {
    float e;
    asm("ex2.approx.f32 %0, %1;" : "=f"(e) : "f"(2.8853900817779268f * x));
    float r;
    asm("rcp.approx.f32 %0, %1;" : "=f"(r) : "f"(1.0f + e));
    return 1.0f - 2.0f * r;
}
// mbarrier ops (CTA-local; no clusters)
__device__ __forceinline__ void minit(uint32_t mbar, uint32_t cnt) {
    asm volatile("mbarrier.init.shared::cta.b64 [%0], %1;" :: "r"(mbar), "r"(cnt) : "memory");
}
__device__ __forceinline__ void mexpect(uint32_t mbar, uint32_t bytes) {
    asm volatile("mbarrier.arrive.expect_tx.shared::cta.b64 _, [%0], %1;"
                 :: "r"(mbar), "r"(bytes) : "memory");
}
__device__ __forceinline__ void mwait(uint32_t mbar, uint32_t ph) {
    asm volatile("{\n\t.reg .pred P;\n"
        "W%=:\n\tmbarrier.try_wait.parity.acquire.cta.shared::cta.b64 P, [%0], %1, 0x989680;\n"
        "\t@P bra D%=;\n\tbra W%=;\nD%=:\n\t}"
        :: "r"(mbar), "r"(ph) : "memory");
}
__device__ __forceinline__ void bulk1d(uint32_t dst, const void* src, uint32_t bytes,
                                       uint32_t mbar) {
    asm volatile("cp.async.bulk.shared::cta.global.mbarrier::complete_tx::bytes "
                 "[%0], [%1], %2, [%3];"
                 :: "r"(dst), "l"(src), "r"(bytes), "r"(mbar) : "memory");
}
__device__ __forceinline__ void fence_async() {
    asm volatile("fence.proxy.async.shared::cta;" ::: "memory");
}

// ---------------- phase 0 ----------------
__global__ void prep_x(const float* __restrict__ x) {
    int t = blockIdx.x;
    for (int i = threadIdx.x; i < 2 * 64 * 136; i += blockDim.x) {
        int mh  = i / (64 * 136);
        int rem = i % (64 * 136);
        int r = rem / 136, f = rem % 136;
        int row = mh * 64 + r;
        float v = (row < NNODE && f < FIN) ? x[(t * NNODE + row) * FIN + f] : 0.0f;
        g_xb2[t][mh][r][f] = __float2bfloat16_rn(v);
    }
}

__global__ void prep_w(const float* __restrict__ Wih, const float* __restrict__ Whh) {
    int c = blockIdx.x;   // 64 column groups
    for (int e = threadIdx.x; e < 3840; e += blockDim.x) {
        int tau = e / 1280;
        int rem = e % 1280;
        int s = rem / 32;
        int l = rem % 32;
        int t = l & 3, g = l >> 2;
        int col = tau * HID + c * 8 + g;
        uint32_t b0, b1;
        if (s < 32) {
            const float* wr = Whh + (size_t)col * HID + s * 16 + t * 2;
            b0 = pk2(wr[0], wr[1]);
            b1 = pk2(wr[8], wr[9]);
        } else {
            const float* wr = Wih + (size_t)col * FIN + (s - 32) * 16 + t * 2;
            b0 = pk2(wr[0], wr[1]);
            b1 = pk2(wr[8], wr[9]);
        }
        g_bpack[c][e] = make_uint2(b0, b1);
    }
    // zero BOTH h buffers exactly (2*2*4*64*136*2 B = 69632 u32 / 64 blocks = 1088)
    uint32_t* hb = (uint32_t*)&g_hb2[0][0][0][0][0];
    for (int i = threadIdx.x; i < 1088; i += blockDim.x)
        hb[c * 1088 + i] = 0u;
}

// ---------------- persistent GRU (gridbar + bulk-async; B-frags reg-cached) ----------------
__global__ void __launch_bounds__(NTH, 1) gru_persistent(
    const float* __restrict__ bih, const float* __restrict__ bhh)
{
    extern __shared__ char sm[];
    char* hS     = sm + HS_OFF;
    char* xS     = sm + XS_OFF;
    uint2* bfS   = (uint2*)(sm + BF_OFF);
    float* biasS = (float*)(sm + BIAS_OFF);
    const uint32_t mb = s2u(sm + MBAR_OFF);   // h: mb+0..24, x: mb+32

    const int tid = threadIdx.x;
    const int w   = tid >> 5;
    const int l   = tid & 31;
    const int m   = (int)(blockIdx.x >> 6);   // row half
    const int gG  = (int)(blockIdx.x & 63);   // column group

    // ---- one-time init ----
    {
        const uint32_t* src = (const uint32_t*)&g_bpack[gG][0];
        uint32_t* dst = (uint32_t*)bfS;
        for (int i = tid; i < BF_BYTES / 4; i += NTH) dst[i] = src[i];
        if (tid < 32) {
            int hu = gG * 8 + (tid & 7);
            int sec = tid >> 3;
            float v;
            if (sec == 0)      v = bih[hu] + bhh[hu];
            else if (sec == 1) v = bih[HID + hu] + bhh[HID + hu];
            else if (sec == 2) v = bhh[2 * HID + hu];
            else               v = bih[2 * HID + hu];
            biasS[tid] = v;
        }
        if (tid == 0) {
            #pragma unroll
            for (int k = 0; k < 5; k++) minit(mb + 8 * k, 1);
        }
    }
    fence_async();
    __syncthreads();
    // prefetch x for step 0
    if (tid == 0) {
        mexpect(mb + 32, CHUNKB);
        bulk1d(s2u(xS), &g_xb2[0][m][0][0], CHUNKB, mb + 32);
    }

    const int rb = w * 16;
    const int gl = l >> 2;
    const int t  = l & 3;
    const int r0g = m * 64 + rb + gl;
    const int r1g = r0g + 8;
    const int colg = gG * 8 + t * 2;
    const int ri0 = r0g & 63, ri1 = r1g & 63;
    const int hcw = colg >> 7, hcc = colg & 127;

    const int arow = rb + (l & 15);
    const uint32_t aBase = (uint32_t)(arow * 272 + ((l >> 4) & 1) * 16);
    const uint32_t aH = s2u(hS) + aBase;
    const uint32_t aX = s2u(xS) + aBase;

    const float brA = biasS[t * 2],      brB = biasS[t * 2 + 1];
    const float bzA = biasS[8 + t * 2],  bzB = biasS[8 + t * 2 + 1];
    const float bhA = biasS[16 + t * 2], bhB = biasS[16 + t * 2 + 1];
    const float bxA = biasS[24 + t * 2], bxB = biasS[24 + t * 2 + 1];

    // ---- register-cache step-invariant B fragments ----
    // x part: all 8 K-steps (s=32..39); h part: first 12 K-steps (s=0..11)
    uint2 bxr[8], bxz[8], bxn[8];
    #pragma unroll
    for (int j = 0; j < 8; j++) {
        bxr[j] = bfS[(0 * 40 + 32 + j) * 32 + l];
        bxz[j] = bfS[(1 * 40 + 32 + j) * 32 + l];
        bxn[j] = bfS[(2 * 40 + 32 + j) * 32 + l];
    }
    uint2 bhr[12], bhz[12], bhn[12];
    #pragma unroll
    for (int s = 0; s < 12; s++) {
        bhr[s] = bfS[(0 * 40 + s) * 32 + l];
        bhz[s] = bfS[(1 * 40 + s) * 32 + l];
        bhn[s] = bfS[(2 * 40 + s) * 32 + l];
    }

    float hm0 = 0.f, hm1 = 0.f, hm2 = 0.f, hm3 = 0.f;
    const uint32_t hS_s = s2u(hS);

    for (int step = 0; step < TSTEPS; step++) {
        const int cur = step & 1, nxt = cur ^ 1;
        const uint32_t ph = (uint32_t)(step & 1);

        // ---- single-thread bulk issue of 4 h chunks ----
        if (tid == 0) {
            #pragma unroll
            for (int c = 0; c < 4; c++) {
                mexpect(mb + 8 * c, CHUNKB);
                bulk1d(hS_s + c * CHUNKB, &g_hb2[cur][m][c][0][0], CHUNKB, mb + 8 * c);
            }
        }

        float accR[4]  = {0.f, 0.f, 0.f, 0.f};
        float accZ[4]  = {0.f, 0.f, 0.f, 0.f};
        float accHN[4] = {0.f, 0.f, 0.f, 0.f};
        float accXN[4] = {0.f, 0.f, 0.f, 0.f};
        uint32_t a0, a1, a2, a3;

        // ---- x part first (prefetched; pure-register B -> hides h chunk-0 latency) ----
        mwait(mb + 32, ph);
        #pragma unroll
        for (int j = 0; j < 8; j++) {
            ldsmx4(aX + (uint32_t)(j * 32), a0, a1, a2, a3);
            mma16816(accR,  a0, a1, a2, a3, bxr[j].x, bxr[j].y);
            mma16816(accZ,  a0, a1, a2, a3, bxz[j].x, bxz[j].y);
            mma16816(accXN, a0, a1, a2, a3, bxn[j].x, bxn[j].y);
        }

        // ---- h chunks, pipelined; s<12 B from registers ----
        #pragma unroll
        for (int c = 0; c < 4; c++) {
            mwait(mb + 8 * c, ph);
            #pragma unroll
            for (int j = 0; j < 8; j++) {
                const int s = c * 8 + j;
                ldsmx4(aH + (uint32_t)(c * CHUNKB + j * 32), a0, a1, a2, a3);
                uint2 br, bz, bn;
                if (s < 12) {
                    br = bhr[s]; bz = bhz[s]; bn = bhn[s];
                } else {
                    br = bfS[(0 * 40 + s) * 32 + l];
                    bz = bfS[(1 * 40 + s) * 32 + l];
                    bn = bfS[(2 * 40 + s) * 32 + l];
                }
                mma16816(accR,  a0, a1, a2, a3, br.x, br.y);
                mma16816(accZ,  a0, a1, a2, a3, bz.x, bz.y);
                mma16816(accHN, a0, a1, a2, a3, bn.x, bn.y);
            }
        }

        // ---- gates (fp32 master h, MUFU approx) ----
        {
            float r = fsig(accR[0] + brA), z = fsig(accZ[0] + bzA);
            float n = ftanh(accXN[0] + bxA + r * (accHN[0] + bhA));
            hm0 = (1.f - z) * n + z * hm0;
        }
        {
            float r = fsig(accR[1] + brB), z = fsig(accZ[1] + bzB);
            float n = ftanh(accXN[1] + bxB + r * (accHN[1] + bhB));
            hm1 = (1.f - z) * n + z * hm1;
        }
        {
            float r = fsig(accR[2] + brA), z = fsig(accZ[2] + bzA);
            float n = ftanh(accXN[2] + bxA + r * (accHN[2] + bhA));
            hm2 = (1.f - z) * n + z * hm2;
        }
        {
            float r = fsig(accR[3] + brB), z = fsig(accZ[3] + bzB);
            float n = ftanh(accXN[3] + bxB + r * (accHN[3] + bhB));
            hm3 = (1.f - z) * n + z * hm3;
        }

        // ---- publish next h (real rows only; chunked padded layout) ----
        if (r0g < NNODE) *(uint32_t*)&g_hb2[nxt][m][hcw][ri0][hcc] = pk2(hm0, hm1);
        if (r1g < NNODE) *(uint32_t*)&g_hb2[nxt][m][hcw][ri1][hcc] = pk2(hm2, hm3);

        if (step == TSTEPS - 1) {
            if (r0g < NNODE) { g_gnn[r0g][colg] = hm0; g_gnn[r0g][colg + 1] = hm1; }
            if (r1g < NNODE) { g_gnn[r1g][colg] = hm2; g_gnn[r1g][colg + 1] = hm3; }
        }

        // ---- grid barrier; x(step+1) prefetch hides inside the wait window ----
        __syncthreads();
        if (tid == 0) {
            if (step + 1 < TSTEPS) {
                mexpect(mb + 32, CHUNKB);
                bulk1d(s2u(xS), &g_xb2[step + 1][m][0][0], CHUNKB, mb + 32);
            }
            unsigned long long old;
            asm volatile("atom.add.release.gpu.u64 %0, [%1], 1;"
                         : "=l"(old) : "l"(&g_bar[step]) : "memory");
            unsigned long long target = (old / (unsigned long long)NCTA) * NCTA + NCTA;
            unsigned long long v;
            do {
                asm volatile("ld.acquire.gpu.u64 %0, [%1];"
                             : "=l"(v) : "l"(&g_bar[step]) : "memory");
            } while (v < target);
        }
        __syncthreads();
    }
}

// ---------------- GNN tail ----------------
__global__ void flat_emb_k(const float* __restrict__ flat, const float* __restrict__ fW,
                           const float* __restrict__ fb, const float* __restrict__ emb) {
    int n = blockIdx.x;
    int o = threadIdx.x;
    float s = fb[o];
    #pragma unroll
    for (int j = 0; j < 32; j++) s += flat[n * 32 + j] * fW[o * 32 + j];
    g_gnn[n][512 + o] = s;
    for (int j = o; j < 128; j += 64) g_gnn[n][576 + j] = emb[n * 128 + j];
}

__global__ void knn_k(const float* __restrict__ emb) {
    __shared__ float eu[128];
    __shared__ float sim[NNODE];
    int u = blockIdx.x;
    eu[threadIdx.x] = emb[u * 128 + threadIdx.x];
    __syncthreads();
    if (threadIdx.x < NNODE) {
        int v = threadIdx.x;
        float d = 0.f, nu = 0.f, nv = 0.f;
        for (int f = 0; f < 128; f++) {
            float a = eu[f], b = emb[v * 128 + f];
            d += a * b; nu += a * a; nv += b * b;
        }
        float s = d / (fmaxf(sqrtf(nu), 1e-8f) * fmaxf(sqrtf(nv), 1e-8f));
        sim[v] = (v == u) ? 0.0f : s;
    }
    __syncthreads();
    if (threadIdx.x == 0) {
        for (int i = 0; i < 8; i++) {
            float best = -1e30f; int bi = 0;
            for (int v = 0; v < NNODE; v++)
                if (sim[v] > best) { best = sim[v]; bi = v; }
            g_tgt[u * 8 + i] = bi;
            sim[bi] = -2e30f;
        }
    }
}

__global__ void build_adj_k() {
    int v = threadIdx.x;
    if (v < NNODE) {
        int c = 0;
        for (int e = 0; e < NNODE * 8; e++)
            if (g_tgt[e] == v) g_srcl[v][c++] = e >> 3;
        g_cnt[v] = c;
    }
}

__global__ void sage1_k(const float* __restrict__ Wl, const float* __restrict__ Wr,
                        const float* __restrict__ b) {
    __shared__ float agg[704];
    __shared__ float xv[704];
    __shared__ int srcl[NNODE];
    __shared__ int scnt;
    int v = blockIdx.x;
    if (threadIdx.x == 0) scnt = g_cnt[v];
    if (threadIdx.x < NNODE) srcl[threadIdx.x] = g_srcl[v][threadIdx.x];
    __syncthreads();
    int cnt = scnt;
    float inv = 1.0f / fmaxf((float)cnt, 1.0f);
    for (int d = threadIdx.x; d < 704; d += blockDim.x) {
        float a = 0.f;
        for (int i = 0; i < cnt; i++) a += g_gnn[srcl[i]][d];
        agg[d] = a * inv;
        xv[d] = g_gnn[v][d];
    }
    __syncthreads();
    int o = threadIdx.x;
    float s = b[o];
    for (int d = 0; d < 704; d++)
        s += Wl[o * 704 + d] * agg[d] + Wr[o * 704 + d] * xv[d];
    g_h1[v][o] = fmaxf(s, 0.0f);
}

__global__ void sage2_k(const float* __restrict__ Wl, const float* __restrict__ Wr,
                        const float* __restrict__ b) {
    __shared__ float agg[256];
    __shared__ float xv[256];
    __shared__ int srcl[NNODE];
    __shared__ int scnt;
    int v = blockIdx.x;
    if (threadIdx.x == 0) scnt = g_cnt[v];
    if (threadIdx.x < NNODE) srcl[threadIdx.x] = g_srcl[v][threadIdx.x];
    __syncthreads();
    int cnt = scnt;
    float inv = 1.0f / fmaxf((float)cnt, 1.0f);
    {
        int d = threadIdx.x;
        float a = 0.f;
        for (int i = 0; i < cnt; i++) a += g_h1[srcl[i]][d];
        agg[d] = a * inv;
        xv[d] = g_h1[v][d];
    }
    __syncthreads();
    if (threadIdx.x < 128) {
        int o = threadIdx.x;
        float s = b[o];
        for (int d = 0; d < 256; d++)
            s += Wl[o * 256 + d] * agg[d] + Wr[o * 256 + d] * xv[d];
        g_g2[v][o] = s;
    }
}

__global__ void out_k(const float* __restrict__ oW, const float* __restrict__ ob,
                      float* __restrict__ out) {
    __shared__ float red[4];
    int v = blockIdx.x;
    float s = 0.f;
    for (int i = threadIdx.x; i < 640; i += 128) {
        float f = (i < 128) ? g_g2[v][i] : g_gnn[v][i - 128];
        s += oW[i] * f;
    }
    for (int off = 16; off > 0; off >>= 1) s += __shfl_down_sync(0xffffffffu, s, off);
    if ((threadIdx.x & 31) == 0) red[threadIdx.x >> 5] = s;
    __syncthreads();
    if (threadIdx.x == 0) {
        float tot = red[0] + red[1] + red[2] + red[3] + ob[0];
        out[v] = 1.0f / (1.0f + expf(-tot));
    }
}

// ---------------- launch ----------------
extern "C" void kernel_launch(void* const* d_in, const int* in_sizes, int n_in,
                              void* d_out, int out_size) {
    const float* node_feat = (const float*)d_in[0];
    const float* flat      = (const float*)d_in[1];
    const float* emb       = (const float*)d_in[2];
    const float* gru_Wih   = (const float*)d_in[3];
    const float* gru_Whh   = (const float*)d_in[4];
    const float* gru_bih   = (const float*)d_in[5];
    const float* gru_bhh   = (const float*)d_in[6];
    const float* flat_W    = (const float*)d_in[7];
    const float* flat_b    = (const float*)d_in[8];
    const float* sage1_Wl  = (const float*)d_in[9];
    const float* sage1_Wr  = (const float*)d_in[10];
    const float* sage1_b   = (const float*)d_in[11];
    const float* sage2_Wl  = (const float*)d_in[12];
    const float* sage2_Wr  = (const float*)d_in[13];
    const float* sage2_b   = (const float*)d_in[14];
    const float* out_W     = (const float*)d_in[15];
    const float* out_b     = (const float*)d_in[16];
    float* out = (float*)d_out;

    static bool attr_set = false;
    if (!attr_set) {
        cudaFuncSetAttribute(gru_persistent,
                             cudaFuncAttributeMaxDynamicSharedMemorySize, SMEM_TOTAL);
        attr_set = true;
    }

    prep_x<<<TSTEPS, 256>>>(node_feat);
    prep_w<<<NCTAN, 256>>>(gru_Wih, gru_Whh);
    flat_emb_k<<<NNODE, 64>>>(flat, flat_W, flat_b, emb);
    knn_k<<<NNODE, 128>>>(emb);
    build_adj_k<<<1, 128>>>();
    gru_persistent<<<NCTA, NTH, SMEM_TOTAL>>>(gru_bih, gru_bhh);
    sage1_k<<<NNODE, 256>>>(sage1_Wl, sage1_Wr, sage1_b);
    sage2_k<<<NNODE, 256>>>(sage2_Wl, sage2_Wr, sage2_b);
    out_k<<<NNODE, 128>>>(out_W, out_b, out);
}